// round 4
// baseline (speedup 1.0000x reference)
#include <cuda_runtime.h>
#include <math.h>

// ---------------- problem constants ----------------
#define Bn     4
#define Pn     12000
#define Nn     32
#define PNn    (Pn*Nn)            // 384000
#define TOTn   (Bn*PNn)           // 1536000
#define HH     282
#define HW2    (HH*HH)            // 79524
#define OH1    278
#define PH1    139
#define OH2    136
#define PH2    68
#define FCIN   (16*PH2*PH2)       // 73984

// ---------------- scratch (static device memory; no allocs) ----------------
__device__ float  g_canvas[(size_t)Bn*128*HW2];       // 162.9 MB
__device__ float  g_conv1 [(size_t)Bn*64*OH1*OH1];    //  79.1 MB
__device__ float  g_pool1 [(size_t)Bn*64*PH1*PH1];    //  19.8 MB
__device__ float  g_conv2 [(size_t)Bn*16*OH2*OH2];
__device__ float  g_pool2 [(size_t)Bn*16*PH2*PH2];
__device__ float  g_feat  [(size_t)Bn*64*Pn];
__device__ int    g_idx   [Bn*Pn];
__device__ double g_mom   [88];       // [0..43] sweep, [44..87] map: 8 means + 36 upper-tri 2nd moments
__device__ double g_c1stats[128];     // 64 sums + 64 sumsq
__device__ double g_c2stats[32];      // 16 sums + 16 sumsq
__device__ float  g_weff  [512];      // folded PFN weight 64x8
__device__ float  g_beff  [64];
__device__ float  g_ab1   [128];      // conv1 alpha[64], beta[64]
__device__ float  g_ab2   [32];       // conv2 alpha[16], beta[16]
__device__ float  g_h     [128];      // fc1 out (4,32)

// ---------------- zeroing ----------------
__global__ void zero_stats_kernel() {
    int t = threadIdx.x;
    if (t < 88)  g_mom[t]     = 0.0;
    if (t < 128) g_c1stats[t] = 0.0;
    if (t < 32)  g_c2stats[t] = 0.0;
}

__global__ void zero_canvas_kernel() {
    size_t t = (size_t)blockIdx.x * blockDim.x + threadIdx.x;
    const size_t n4 = ((size_t)Bn*128*HW2) / 4;
    if (t < n4) {
        float4 z = make_float4(0.f, 0.f, 0.f, 0.f);
        ((float4*)g_canvas)[t] = z;
    }
}

// ---------------- PFN: raw-input moments (for analytic BN stats) ----------------
// off selects the 44-slot region of g_mom (0 = sweep, 44 = map).
__global__ void pfn_mom_kernel(const float* __restrict__ x, int off) {
    float a[44];
#pragma unroll
    for (int k = 0; k < 44; k++) a[k] = 0.f;

    for (int i = blockIdx.x * blockDim.x + threadIdx.x; i < TOTn; i += gridDim.x * blockDim.x) {
        int b = i / PNn, r = i % PNn;
        const float* p = x + (size_t)b * 8 * PNn + r;
        float v[8];
#pragma unroll
        for (int c = 0; c < 8; c++) v[c] = p[(size_t)c * PNn];
#pragma unroll
        for (int c = 0; c < 8; c++) a[c] += v[c];
        int k = 8;
#pragma unroll
        for (int c = 0; c < 8; c++)
#pragma unroll
            for (int c2 = c; c2 < 8; c2++)
                a[k++] += v[c] * v[c2];
    }

    __shared__ double sm[44];
    if (threadIdx.x < 44) sm[threadIdx.x] = 0.0;
    __syncthreads();
    int lane = threadIdx.x & 31;
#pragma unroll
    for (int k = 0; k < 44; k++) {
        float s = a[k];
#pragma unroll
        for (int o = 16; o > 0; o >>= 1) s += __shfl_down_sync(0xffffffffu, s, o);
        if (lane == 0) atomicAdd(&sm[k], (double)s);
    }
    __syncthreads();
    if (threadIdx.x < 44) atomicAdd(&g_mom[off + threadIdx.x], sm[threadIdx.x]);
}

// Fold BN(train stats) into effective weight/bias. Streaming form: no M[8][8]
// array (the R3 version spilled ~440 B/thread of doubles -> 128 MB local pool).
// y = Wx+b is linear, so per-channel mean/var follow from input means m[8] and
// second moments M (upper-tri, streamed from g_mom with x2 off-diagonal weight).
__global__ void pfn_fin_kernel(int off,
                               const float* __restrict__ w, const float* __restrict__ bias,
                               const float* __restrict__ g, const float* __restrict__ be) {
    int o = threadIdx.x;
    if (o >= 64) return;
    const double invNT = 1.0 / (double)TOTn;

    double wv[8];
#pragma unroll
    for (int c = 0; c < 8; c++) wv[c] = (double)w[o * 8 + c];
    double bo = (double)bias[o];

    double mu = bo;
#pragma unroll
    for (int c = 0; c < 8; c++) mu += wv[c] * (g_mom[off + c] * invNT);

    double quad = 0.0;
    int k = 8;
#pragma unroll
    for (int c = 0; c < 8; c++)
#pragma unroll
        for (int c2 = c; c2 < 8; c2++) {
            double Mv = g_mom[off + k] * invNT;
            k++;
            double t = wv[c] * wv[c2] * Mv;
            quad += (c == c2) ? t : (2.0 * t);
        }

    double ey2 = bo * bo + 2.0 * bo * (mu - bo) + quad;
    double var = ey2 - mu * mu;
    double alpha = (double)g[o] / sqrt(var + 1e-5);
    double beta  = (double)be[o] - mu * alpha;
#pragma unroll
    for (int c = 0; c < 8; c++) g_weff[o * 8 + c] = (float)(alpha * wv[c]);
    g_beff[o] = (float)(alpha * bo + beta);
}

// PFN pass 2: per-(b,p) warp; lane = point n. Fused matvec + ReLU + warp-max. Also emits grid index.
__global__ void pfn_max_kernel(const float* __restrict__ x) {
    __shared__ float swf[512];
    __shared__ float sbf[64];
    int tid = threadIdx.x;
    for (int i = tid; i < 512; i += 256) swf[i] = g_weff[i];
    if (tid < 64) sbf[tid] = g_beff[tid];
    __syncthreads();

    int warp = (blockIdx.x * 256 + tid) >> 5;
    int lane = tid & 31;
    if (warp >= Bn * Pn) return;
    int b = warp / Pn, p = warp % Pn;

    const float* xb = x + ((size_t)b * 8 * Pn + p) * Nn + lane;
    float xv[8];
#pragma unroll
    for (int c = 0; c < 8; c++) xv[c] = xb[(size_t)c * PNn];

    if (lane == 0) {
        int gx = (int)floorf((xv[0] + 22.0f) / 0.16f);
        int gy = (int)floorf((xv[1] + 22.0f) / 0.16f);
        g_idx[b * Pn + p] = gx * HH + gy;
    }

    for (int o = 0; o < 64; o++) {
        float y = sbf[o];
#pragma unroll
        for (int c = 0; c < 8; c++) y = fmaf(swf[o * 8 + c], xv[c], y);
        y = fmaxf(y, 0.f);
#pragma unroll
        for (int off = 16; off > 0; off >>= 1) y = fmaxf(y, __shfl_xor_sync(0xffffffffu, y, off));
        if (lane == 0) g_feat[((size_t)b * 64 + o) * Pn + p] = y;
    }
}

__global__ void scatter_kernel(int cbase) {
    int t = blockIdx.x * 256 + threadIdx.x;
    if (t >= Bn * 64 * Pn) return;
    int p  = t % Pn;
    int bo = t / Pn;         // b*64 + o
    int b  = bo >> 6;
    int o  = bo & 63;
    float v = g_feat[t];
    int idx = g_idx[b * Pn + p];
    g_canvas[((size_t)(b * 128 + cbase + o)) * HW2 + idx] = v;
}

// ---------------- conv1: 5x5, 128->64, tile 32x64, 8 oc/block, thread = 2x4 px ----------------
__global__ __launch_bounds__(256, 1) void conv1_kernel(const float* __restrict__ wc1,
                                                       const float* __restrict__ bc1) {
    __shared__ float sp[36][72];
    __shared__ float sw[200];
    __shared__ double ssum[8], ssq[8];
    int tid = threadIdx.x;
    int b   = blockIdx.z >> 3, ocg = blockIdx.z & 7;
    int oy  = blockIdx.y * 32, ox = blockIdx.x * 64;
    if (tid < 8) { ssum[tid] = 0.0; ssq[tid] = 0.0; }

    float acc[8][8];
#pragma unroll
    for (int i = 0; i < 8; i++)
#pragma unroll
        for (int j = 0; j < 8; j++) acc[i][j] = 0.f;

    const float* cb = g_canvas + (size_t)b * 128 * HW2;
    int r0 = (tid >> 4) * 2, c0 = (tid & 15) * 4;

    for (int ci = 0; ci < 128; ci++) {
        __syncthreads();
        const float* src = cb + (size_t)ci * HW2;
        for (int i = tid; i < 36 * 68; i += 256) {
            int r = i / 68, c = i % 68;
            int gy = oy + r, gx = ox + c;
            sp[r][c] = (gy < HH && gx < HH) ? src[gy * HH + gx] : 0.f;
        }
        if (tid < 200) sw[tid] = wc1[((ocg * 8 + tid / 25) * 128 + ci) * 25 + (tid % 25)];
        __syncthreads();

        float pr[6][8];
#pragma unroll
        for (int i = 0; i < 6; i++)
#pragma unroll
            for (int j = 0; j < 8; j++) pr[i][j] = sp[r0 + i][c0 + j];

#pragma unroll
        for (int oc = 0; oc < 8; oc++)
#pragma unroll
            for (int ky = 0; ky < 5; ky++)
#pragma unroll
                for (int kx = 0; kx < 5; kx++) {
                    float wv = sw[oc * 25 + ky * 5 + kx];
#pragma unroll
                    for (int iy = 0; iy < 2; iy++)
#pragma unroll
                        for (int ix = 0; ix < 4; ix++)
                            acc[oc][iy * 4 + ix] = fmaf(pr[ky + iy][kx + ix], wv, acc[oc][iy * 4 + ix]);
                }
    }

    int lane = tid & 31;
#pragma unroll
    for (int oc = 0; oc < 8; oc++) {
        float bias = bc1[ocg * 8 + oc];
        float s = 0.f, sq = 0.f;
#pragma unroll
        for (int iy = 0; iy < 2; iy++)
#pragma unroll
            for (int ix = 0; ix < 4; ix++) {
                int ro = oy + r0 + iy, co = ox + c0 + ix;
                if (ro < OH1 && co < OH1) {
                    float y = acc[oc][iy * 4 + ix] + bias;
                    g_conv1[(((size_t)b * 64 + ocg * 8 + oc) * OH1 + ro) * OH1 + co] = y;
                    s += y; sq += y * y;
                }
            }
#pragma unroll
        for (int off = 16; off > 0; off >>= 1) {
            s  += __shfl_down_sync(0xffffffffu, s,  off);
            sq += __shfl_down_sync(0xffffffffu, sq, off);
        }
        if (lane == 0) { atomicAdd(&ssum[oc], (double)s); atomicAdd(&ssq[oc], (double)sq); }
    }
    __syncthreads();
    if (tid < 8) {
        atomicAdd(&g_c1stats[ocg * 8 + tid],      ssum[tid]);
        atomicAdd(&g_c1stats[64 + ocg * 8 + tid], ssq[tid]);
    }
}

// generic BN finalize (training stats) -> alpha/beta. which: 1 = conv1 (C=64), 2 = conv2 (C=16)
__global__ void bn_fin_kernel(int which,
                              const float* __restrict__ g, const float* __restrict__ be,
                              double invN) {
    int C = (which == 1) ? 64 : 16;
    const double* stats = (which == 1) ? g_c1stats : g_c2stats;
    float* ab           = (which == 1) ? g_ab1     : g_ab2;
    int c = threadIdx.x;
    if (c >= C) return;
    double mean = stats[c] * invN;
    double var  = stats[C + c] * invN - mean * mean;
    double alpha = (double)g[c] / sqrt(var + 1e-5);
    double beta  = (double)be[c] - mean * alpha;
    ab[c]     = (float)alpha;
    ab[C + c] = (float)beta;
}

__global__ void pool1_kernel() {
    int t = blockIdx.x * 256 + threadIdx.x;
    if (t >= Bn * 64 * PH1 * PH1) return;
    int j = t % PH1; int tmp = t / PH1;
    int i = tmp % PH1; tmp /= PH1;
    int c = tmp % 64;  int b = tmp / 64;
    float a = g_ab1[c], bt = g_ab1[64 + c];
    size_t base = (((size_t)b * 64 + c) * OH1 + 2 * i) * OH1 + 2 * j;
    float v0 = fmaf(a, g_conv1[base],        bt);
    float v1 = fmaf(a, g_conv1[base + 1],    bt);
    float v2 = fmaf(a, g_conv1[base + OH1],  bt);
    float v3 = fmaf(a, g_conv1[base + OH1 + 1], bt);
    float r = fmaxf(fmaxf(v0, v1), fmaxf(v2, v3));
    g_pool1[t] = fmaxf(r, 0.f);
}

// ---------------- conv2: 4x4, 64->16, tile 32x32, 8 oc/block, thread = 2x2 px ----------------
__global__ __launch_bounds__(256) void conv2_kernel(const float* __restrict__ wc2,
                                                    const float* __restrict__ bc2) {
    __shared__ float sp[35][36];
    __shared__ float sw[128];
    __shared__ double ssum[8], ssq[8];
    int tid = threadIdx.x;
    int b   = blockIdx.z >> 1, ocg = blockIdx.z & 1;
    int oy  = blockIdx.y * 32, ox = blockIdx.x * 32;
    if (tid < 8) { ssum[tid] = 0.0; ssq[tid] = 0.0; }

    float acc[8][4];
#pragma unroll
    for (int i = 0; i < 8; i++)
#pragma unroll
        for (int j = 0; j < 4; j++) acc[i][j] = 0.f;

    const float* cb = g_pool1 + (size_t)b * 64 * PH1 * PH1;
    int r0 = (tid >> 4) * 2, c0 = (tid & 15) * 2;

    for (int ci = 0; ci < 64; ci++) {
        __syncthreads();
        const float* src = cb + (size_t)ci * PH1 * PH1;
        for (int i = tid; i < 35 * 35; i += 256) {
            int r = i / 35, c = i % 35;
            int gy = oy + r, gx = ox + c;
            sp[r][c] = (gy < PH1 && gx < PH1) ? src[gy * PH1 + gx] : 0.f;
        }
        if (tid < 128) sw[tid] = wc2[((ocg * 8 + (tid >> 4)) * 64 + ci) * 16 + (tid & 15)];
        __syncthreads();

        float pr[5][5];
#pragma unroll
        for (int i = 0; i < 5; i++)
#pragma unroll
            for (int j = 0; j < 5; j++) pr[i][j] = sp[r0 + i][c0 + j];

#pragma unroll
        for (int oc = 0; oc < 8; oc++)
#pragma unroll
            for (int ky = 0; ky < 4; ky++)
#pragma unroll
                for (int kx = 0; kx < 4; kx++) {
                    float wv = sw[oc * 16 + ky * 4 + kx];
#pragma unroll
                    for (int iy = 0; iy < 2; iy++)
#pragma unroll
                        for (int ix = 0; ix < 2; ix++)
                            acc[oc][iy * 2 + ix] = fmaf(pr[ky + iy][kx + ix], wv, acc[oc][iy * 2 + ix]);
                }
    }

    int lane = tid & 31;
#pragma unroll
    for (int oc = 0; oc < 8; oc++) {
        float bias = bc2[ocg * 8 + oc];
        float s = 0.f, sq = 0.f;
#pragma unroll
        for (int iy = 0; iy < 2; iy++)
#pragma unroll
            for (int ix = 0; ix < 2; ix++) {
                int ro = oy + r0 + iy, co = ox + c0 + ix;
                if (ro < OH2 && co < OH2) {
                    float y = acc[oc][iy * 2 + ix] + bias;
                    g_conv2[(((size_t)b * 16 + ocg * 8 + oc) * OH2 + ro) * OH2 + co] = y;
                    s += y; sq += y * y;
                }
            }
#pragma unroll
        for (int off = 16; off > 0; off >>= 1) {
            s  += __shfl_down_sync(0xffffffffu, s,  off);
            sq += __shfl_down_sync(0xffffffffu, sq, off);
        }
        if (lane == 0) { atomicAdd(&ssum[oc], (double)s); atomicAdd(&ssq[oc], (double)sq); }
    }
    __syncthreads();
    if (tid < 8) {
        atomicAdd(&g_c2stats[ocg * 8 + tid],      ssum[tid]);
        atomicAdd(&g_c2stats[16 + ocg * 8 + tid], ssq[tid]);
    }
}

__global__ void pool2_kernel() {
    int t = blockIdx.x * 256 + threadIdx.x;
    if (t >= Bn * 16 * PH2 * PH2) return;
    int j = t % PH2; int tmp = t / PH2;
    int i = tmp % PH2; tmp /= PH2;
    int c = tmp % 16;  int b = tmp / 16;
    float a = g_ab2[c], bt = g_ab2[16 + c];
    size_t base = (((size_t)b * 16 + c) * OH2 + 2 * i) * OH2 + 2 * j;
    float v0 = fmaf(a, g_conv2[base],            bt);
    float v1 = fmaf(a, g_conv2[base + 1],        bt);
    float v2 = fmaf(a, g_conv2[base + OH2],      bt);
    float v3 = fmaf(a, g_conv2[base + OH2 + 1],  bt);
    float r = fmaxf(fmaxf(v0, v1), fmaxf(v2, v3));
    g_pool2[t] = fmaxf(r, 0.f);
}

// ---------------- fc1: block per (j,b) dot over 73984 ----------------
__global__ void fc1_kernel(const float* __restrict__ w, const float* __restrict__ bias) {
    int j = blockIdx.x, b = blockIdx.y, tid = threadIdx.x;
    const float* x  = g_pool2 + (size_t)b * FCIN;
    const float* wr = w + (size_t)j * FCIN;
    float s = 0.f;
    for (int i = tid; i < FCIN; i += 256) s = fmaf(x[i], wr[i], s);
    __shared__ float red[256];
    red[tid] = s;
    __syncthreads();
    for (int k = 128; k > 0; k >>= 1) {
        if (tid < k) red[tid] += red[tid + k];
        __syncthreads();
    }
    if (tid == 0) g_h[b * 32 + j] = red[0] + bias[j];
}

// ---------------- head: batch-BN(4 samples) + tanh + 3-way output ----------------
__global__ void head_kernel(const float* __restrict__ gfc, const float* __restrict__ befc,
                            const float* __restrict__ wout, const float* __restrict__ bout,
                            float* __restrict__ out) {
    __shared__ float hn[4][32];
    int t = threadIdx.x;
    if (t < 32) {
        float h0 = g_h[t], h1 = g_h[32 + t], h2 = g_h[64 + t], h3 = g_h[96 + t];
        float m = 0.25f * (h0 + h1 + h2 + h3);
        float d0 = h0 - m, d1 = h1 - m, d2 = h2 - m, d3 = h3 - m;
        float v = 0.25f * (d0 * d0 + d1 * d1 + d2 * d2 + d3 * d3);
        float inv = rsqrtf(v + 1e-5f);
        float gg = gfc[t], bb = befc[t];
        hn[0][t] = tanhf(fmaf(d0 * inv, gg, bb));
        hn[1][t] = tanhf(fmaf(d1 * inv, gg, bb));
        hn[2][t] = tanhf(fmaf(d2 * inv, gg, bb));
        hn[3][t] = tanhf(fmaf(d3 * inv, gg, bb));
    }
    __syncthreads();
    if (t < 12) {
        int b = t / 3, k = t % 3;
        float s = bout[k];
#pragma unroll
        for (int j = 0; j < 32; j++) s = fmaf(hn[b][j], wout[k * 32 + j], s);
        out[b * 3 + k] = s;
    }
}

// ---------------- launch ----------------
extern "C" void kernel_launch(void* const* d_in, const int* in_sizes, int n_in,
                              void* d_out, int out_size) {
    const float* sweep   = (const float*)d_in[0];
    const float* map_pts = (const float*)d_in[1];
    const float* w_pfn_s = (const float*)d_in[2];
    const float* b_pfn_s = (const float*)d_in[3];
    const float* g_pfn_s = (const float*)d_in[4];
    const float* be_pfn_s= (const float*)d_in[5];
    const float* w_pfn_m = (const float*)d_in[6];
    const float* b_pfn_m = (const float*)d_in[7];
    const float* g_pfn_m = (const float*)d_in[8];
    const float* be_pfn_m= (const float*)d_in[9];
    const float* w_c1    = (const float*)d_in[10];
    const float* b_c1    = (const float*)d_in[11];
    const float* g_c1    = (const float*)d_in[12];
    const float* be_c1   = (const float*)d_in[13];
    const float* w_c2    = (const float*)d_in[14];
    const float* b_c2    = (const float*)d_in[15];
    const float* g_c2    = (const float*)d_in[16];
    const float* be_c2   = (const float*)d_in[17];
    const float* w_fc1   = (const float*)d_in[18];
    const float* b_fc1   = (const float*)d_in[19];
    const float* g_fc1   = (const float*)d_in[20];
    const float* be_fc1  = (const float*)d_in[21];
    const float* w_out   = (const float*)d_in[22];
    const float* b_out   = (const float*)d_in[23];
    float* out = (float*)d_out;

    // reset accumulators + canvas
    zero_stats_kernel<<<1, 128>>>();
    {
        int n4 = (int)(((size_t)Bn * 128 * HW2) / 4);
        zero_canvas_kernel<<<(n4 + 255) / 256, 256>>>();
    }

    // PFN moments (sweep then map), analytic BN fold
    pfn_mom_kernel<<<1024, 256>>>(sweep,   0);
    pfn_mom_kernel<<<1024, 256>>>(map_pts, 44);

    // sweep branch: fold -> pfn pass2 -> scatter (channels 0..63)
    pfn_fin_kernel<<<1, 64>>>(0, w_pfn_s, b_pfn_s, g_pfn_s, be_pfn_s);
    pfn_max_kernel<<<(Bn * Pn) / 8, 256>>>(sweep);
    scatter_kernel<<<(Bn * 64 * Pn) / 256, 256>>>(0);

    // map branch: fold -> pfn pass2 -> scatter (channels 64..127)
    pfn_fin_kernel<<<1, 64>>>(44, w_pfn_m, b_pfn_m, g_pfn_m, be_pfn_m);
    pfn_max_kernel<<<(Bn * Pn) / 8, 256>>>(map_pts);
    scatter_kernel<<<(Bn * 64 * Pn) / 256, 256>>>(64);

    // conv1 + BN + pool
    conv1_kernel<<<dim3(5, 9, 32), 256>>>(w_c1, b_c1);
    bn_fin_kernel<<<1, 64>>>(1, g_c1, be_c1, 1.0 / ((double)Bn * OH1 * OH1));
    pool1_kernel<<<(Bn * 64 * PH1 * PH1 + 255) / 256, 256>>>();

    // conv2 + BN + pool
    conv2_kernel<<<dim3(5, 5, 8), 256>>>(w_c2, b_c2);
    bn_fin_kernel<<<1, 32>>>(2, g_c2, be_c2, 1.0 / ((double)Bn * OH2 * OH2));
    pool2_kernel<<<(Bn * 16 * PH2 * PH2) / 256, 256>>>();

    // fc1 + head
    fc1_kernel<<<dim3(32, 4), 256>>>(w_fc1, b_fc1);
    head_kernel<<<1, 64>>>(g_fc1, be_fc1, w_out, b_out, out);
}